// round 2
// baseline (speedup 1.0000x reference)
#include <cuda_runtime.h>
#include <math.h>

#define BB 2
#define NN 2048
#define DD 256
#define HH 8
#define DH 32

// Scratch (allocation-free rule: __device__ globals)
__device__ float g_Q[BB*HH*NN*DH];
__device__ float g_K[BB*HH*NN*DH];
__device__ float g_V[BB*HH*NN*DH];
__device__ float g_attnout[BB*NN*DD];

// ---------------------------------------------------------------------------
// QKV projection GEMM: C[r][c] = sum_k x[r][k] * W[c][k]
// Output scattered to [b][h][n][d] layout.  grid = (64, 4, 3), 256 thr.
// ---------------------------------------------------------------------------
__global__ void gemm_qkv(const float* __restrict__ x,
                         const float* __restrict__ Wq,
                         const float* __restrict__ Wk,
                         const float* __restrict__ Wv) {
    const float* W;
    float* dst;
    int z = blockIdx.z;
    if (z == 0)      { W = Wq; dst = g_Q; }
    else if (z == 1) { W = Wk; dst = g_K; }
    else             { W = Wv; dst = g_V; }

    __shared__ float As[16][65];
    __shared__ float Ws[16][65];

    int t = threadIdx.x;
    int r0 = blockIdx.x * 64;
    int c0 = blockIdx.y * 64;
    int lrow = t >> 2;       // 0..63
    int lkc  = t & 3;        // 0..3  (float4 chunk within 16-wide k tile)
    int tm = t >> 4;         // 0..15
    int tn = t & 15;         // 0..15

    float acc[4][4];
    #pragma unroll
    for (int i = 0; i < 4; i++)
        #pragma unroll
        for (int j = 0; j < 4; j++) acc[i][j] = 0.f;

    for (int k0 = 0; k0 < DD; k0 += 16) {
        __syncthreads();
        float4 a4 = *(const float4*)&x[(size_t)(r0 + lrow) * DD + k0 + lkc * 4];
        As[lkc*4+0][lrow] = a4.x; As[lkc*4+1][lrow] = a4.y;
        As[lkc*4+2][lrow] = a4.z; As[lkc*4+3][lrow] = a4.w;
        float4 w4 = *(const float4*)&W[(size_t)(c0 + lrow) * DD + k0 + lkc * 4];
        Ws[lkc*4+0][lrow] = w4.x; Ws[lkc*4+1][lrow] = w4.y;
        Ws[lkc*4+2][lrow] = w4.z; Ws[lkc*4+3][lrow] = w4.w;
        __syncthreads();

        #pragma unroll
        for (int k = 0; k < 16; k++) {
            float a[4], b[4];
            #pragma unroll
            for (int i = 0; i < 4; i++) a[i] = As[k][tm*4 + i];
            #pragma unroll
            for (int j = 0; j < 4; j++) b[j] = Ws[k][tn*4 + j];
            #pragma unroll
            for (int i = 0; i < 4; i++)
                #pragma unroll
                for (int j = 0; j < 4; j++)
                    acc[i][j] += a[i] * b[j];
        }
    }

    #pragma unroll
    for (int i = 0; i < 4; i++) {
        int r = r0 + tm*4 + i;
        int b = r >> 11;          // / NN
        int n = r & (NN - 1);
        #pragma unroll
        for (int j = 0; j < 4; j++) {
            int c = c0 + tn*4 + j;
            int h = c >> 5;
            int d = c & 31;
            dst[(((size_t)(b*HH + h) * NN) + n) * DH + d] = acc[i][j];
        }
    }
}

// ---------------------------------------------------------------------------
// Masked attention with online softmax.
// grid = (N/32, H, B), 256 threads. 8-lane group per query row.
// ---------------------------------------------------------------------------
__global__ void attn_kernel(const float* __restrict__ adj) {
    __shared__ float Qs[32][33];
    __shared__ float Ks[64][33];
    __shared__ float Vs[64][33];
    __shared__ float Ad[32][65];

    int b  = blockIdx.z;
    int h  = blockIdx.y;
    int q0 = blockIdx.x * 32;
    int t  = threadIdx.x;

    const float* Qg = g_Q + (size_t)(b*HH + h) * NN * DH;
    const float* Kg = g_K + (size_t)(b*HH + h) * NN * DH;
    const float* Vg = g_V + (size_t)(b*HH + h) * NN * DH;
    const float* Ag = adj + ((size_t)b * NN + q0) * NN;

    // Load Q tile once
    for (int idx = t; idx < 32*32; idx += 256) {
        int r = idx >> 5, c = idx & 31;
        Qs[r][c] = Qg[(size_t)(q0 + r) * DH + c];
    }

    int tq  = t >> 3;   // query row 0..31
    int tm8 = t & 7;    // lane within 8-group

    float o[32];
    #pragma unroll
    for (int d = 0; d < 32; d++) o[d] = 0.f;
    float rmax = -1e30f, rsum = 0.f;
    const float scale = 0.17677669529663688f;  // 1/sqrt(32)

    for (int m0 = 0; m0 < NN; m0 += 64) {
        __syncthreads();
        for (int idx = t; idx < 64*32; idx += 256) {
            int r = idx >> 5, c = idx & 31;
            Ks[r][c] = Kg[(size_t)(m0 + r) * DH + c];
            Vs[r][c] = Vg[(size_t)(m0 + r) * DH + c];
        }
        for (int idx = t; idx < 32*64; idx += 256) {
            int r = idx >> 6, c = idx & 63;
            Ad[r][c] = Ag[(size_t)r * NN + m0 + c];
        }
        __syncthreads();

        // scores: s[j] = q . k_{tm8+8j}
        float s[8];
        #pragma unroll
        for (int j = 0; j < 8; j++) s[j] = 0.f;
        #pragma unroll
        for (int d = 0; d < 32; d++) {
            float qv = Qs[tq][d];
            #pragma unroll
            for (int j = 0; j < 8; j++)
                s[j] += qv * Ks[tm8 + 8*j][d];
        }

        float tmax = -3.0e38f;
        #pragma unroll
        for (int j = 0; j < 8; j++) {
            s[j] *= scale;
            if (Ad[tq][tm8 + 8*j] == 0.f) s[j] = -3.0e38f;
            tmax = fmaxf(tmax, s[j]);
        }
        tmax = fmaxf(tmax, __shfl_xor_sync(0xffffffffu, tmax, 1));
        tmax = fmaxf(tmax, __shfl_xor_sync(0xffffffffu, tmax, 2));
        tmax = fmaxf(tmax, __shfl_xor_sync(0xffffffffu, tmax, 4));

        float nmax = fmaxf(rmax, tmax);
        float corr = __expf(rmax - nmax);
        rsum *= corr;
        #pragma unroll
        for (int d = 0; d < 32; d++) o[d] *= corr;

        float lsum = 0.f;
        #pragma unroll
        for (int j = 0; j < 8; j++) {
            s[j] = __expf(s[j] - nmax);   // masked: exp(~-3e38) -> 0
            lsum += s[j];
        }
        lsum += __shfl_xor_sync(0xffffffffu, lsum, 1);
        lsum += __shfl_xor_sync(0xffffffffu, lsum, 2);
        lsum += __shfl_xor_sync(0xffffffffu, lsum, 4);
        rsum += lsum;
        rmax = nmax;

        // o += P * V
        #pragma unroll
        for (int d = 0; d < 32; d++) {
            float acc = 0.f;
            #pragma unroll
            for (int j = 0; j < 8; j++)
                acc += s[j] * Vs[tm8 + 8*j][d];
            o[d] += acc;
        }
    }

    // reduce o across the 8-lane group
    #pragma unroll
    for (int d = 0; d < 32; d++) {
        o[d] += __shfl_xor_sync(0xffffffffu, o[d], 1);
        o[d] += __shfl_xor_sync(0xffffffffu, o[d], 2);
        o[d] += __shfl_xor_sync(0xffffffffu, o[d], 4);
    }
    float inv = 1.0f / rsum;

    // each of the 8 lanes writes 4 consecutive d's (concat-head layout)
    float* Og = g_attnout + ((size_t)(b * NN + q0 + tq)) * DD + h * DH;
    #pragma unroll
    for (int u = 0; u < 4; u++)
        Og[tm8*4 + u] = o[tm8*4 + u] * inv;
}

// ---------------------------------------------------------------------------
// Output projection: out[r][c] = sum_k attnout[r][k] * Wo[c][k] + bo[c]
// grid = (64, 4), 256 thr.
// ---------------------------------------------------------------------------
__global__ void gemm_out(const float* __restrict__ Wo,
                         const float* __restrict__ bo,
                         float* __restrict__ out) {
    __shared__ float As[16][65];
    __shared__ float Ws[16][65];

    int t = threadIdx.x;
    int r0 = blockIdx.x * 64;
    int c0 = blockIdx.y * 64;
    int lrow = t >> 2;
    int lkc  = t & 3;
    int tm = t >> 4;
    int tn = t & 15;

    float acc[4][4];
    #pragma unroll
    for (int i = 0; i < 4; i++)
        #pragma unroll
        for (int j = 0; j < 4; j++) acc[i][j] = 0.f;

    for (int k0 = 0; k0 < DD; k0 += 16) {
        __syncthreads();
        float4 a4 = *(const float4*)&g_attnout[(size_t)(r0 + lrow) * DD + k0 + lkc * 4];
        As[lkc*4+0][lrow] = a4.x; As[lkc*4+1][lrow] = a4.y;
        As[lkc*4+2][lrow] = a4.z; As[lkc*4+3][lrow] = a4.w;
        float4 w4 = *(const float4*)&Wo[(size_t)(c0 + lrow) * DD + k0 + lkc * 4];
        Ws[lkc*4+0][lrow] = w4.x; Ws[lkc*4+1][lrow] = w4.y;
        Ws[lkc*4+2][lrow] = w4.z; Ws[lkc*4+3][lrow] = w4.w;
        __syncthreads();

        #pragma unroll
        for (int k = 0; k < 16; k++) {
            float a[4], b[4];
            #pragma unroll
            for (int i = 0; i < 4; i++) a[i] = As[k][tm*4 + i];
            #pragma unroll
            for (int j = 0; j < 4; j++) b[j] = Ws[k][tn*4 + j];
            #pragma unroll
            for (int i = 0; i < 4; i++)
                #pragma unroll
                for (int j = 0; j < 4; j++)
                    acc[i][j] += a[i] * b[j];
        }
    }

    #pragma unroll
    for (int i = 0; i < 4; i++) {
        int r = r0 + tm*4 + i;
        #pragma unroll
        for (int j = 0; j < 4; j++) {
            int c = c0 + tn*4 + j;
            out[(size_t)r * DD + c] = acc[i][j] + bo[c];
        }
    }
}

extern "C" void kernel_launch(void* const* d_in, const int* in_sizes, int n_in,
                              void* d_out, int out_size) {
    const float* x   = (const float*)d_in[0];
    const float* adj = (const float*)d_in[1];
    const float* Wq  = (const float*)d_in[2];
    const float* Wk  = (const float*)d_in[3];
    const float* Wv  = (const float*)d_in[4];
    const float* Wo  = (const float*)d_in[5];
    const float* bo  = (const float*)d_in[6];
    float* out = (float*)d_out;

    gemm_qkv<<<dim3(64, 4, 3), 256>>>(x, Wq, Wk, Wv);
    attn_kernel<<<dim3(NN/32, HH, BB), 256>>>(adj);
    gemm_out<<<dim3(64, 4), 256>>>(Wo, bo, out);
}

// round 6
// speedup vs baseline: 1.7824x; 1.7824x over previous
#include <cuda_runtime.h>
#include <math.h>

#define BB 2
#define NN 2048
#define DD 256
#define HH 8
#define DH 32
#define R_ROWS (BB*HH*NN)

// Scratch (allocation-free rule: __device__ globals)
__device__ float g_Q[BB*HH*NN*DH];
__device__ float g_K[BB*HH*NN*DH];
__device__ float g_V[BB*HH*NN*DH];
__device__ float g_po[2 * R_ROWS * DH];   // unnormalized partial outputs (2 key-halves)
__device__ float g_pm[2 * R_ROWS * 2];    // per-row (max, sum) per key-half
__device__ float g_attnout[BB*NN*DD];

// ---------------------------------------------------------------------------
// 128x64-tile fp32 GEMM, 256 threads, 8x4 micro-tile, k-stage 16.
// C[r][c] = sum_k A[r][k] * W[c][k]
// ---------------------------------------------------------------------------

// QKV projection: grid (32, 4, 3)
__global__ void __launch_bounds__(256) gemm_qkv(const float* __restrict__ x,
                         const float* __restrict__ Wq,
                         const float* __restrict__ Wk,
                         const float* __restrict__ Wv) {
    const float* W;
    float* dst;
    int z = blockIdx.z;
    if (z == 0)      { W = Wq; dst = g_Q; }
    else if (z == 1) { W = Wk; dst = g_K; }
    else             { W = Wv; dst = g_V; }

    __shared__ float Ast[16][132];
    __shared__ float Wst[16][68];

    int t  = threadIdx.x;
    int tq = t >> 4;       // 0..15 -> 8 rows each
    int tc = t & 15;       // 0..15 -> 4 cols each
    int r0 = blockIdx.x * 128;
    int c0 = blockIdx.y * 64;

    float acc[8][4];
    #pragma unroll
    for (int i = 0; i < 8; i++)
        #pragma unroll
        for (int j = 0; j < 4; j++) acc[i][j] = 0.f;

    for (int k0 = 0; k0 < DD; k0 += 16) {
        __syncthreads();
        #pragma unroll
        for (int rep = 0; rep < 2; rep++) {
            int idx = t + rep * 256;           // 512 float4 of A
            int row = idx >> 2;
            int kc  = (idx & 3) * 4;
            float4 a = *(const float4*)&x[(size_t)(r0 + row) * DD + k0 + kc];
            Ast[kc+0][row] = a.x; Ast[kc+1][row] = a.y;
            Ast[kc+2][row] = a.z; Ast[kc+3][row] = a.w;
        }
        {
            int idx = t;                        // 256 float4 of W
            int col = idx >> 2;
            int kc  = (idx & 3) * 4;
            float4 w = *(const float4*)&W[(size_t)(c0 + col) * DD + k0 + kc];
            Wst[kc+0][col] = w.x; Wst[kc+1][col] = w.y;
            Wst[kc+2][col] = w.z; Wst[kc+3][col] = w.w;
        }
        __syncthreads();

        #pragma unroll
        for (int k = 0; k < 16; k++) {
            float4 a0 = *(const float4*)&Ast[k][tq*8];
            float4 a1 = *(const float4*)&Ast[k][tq*8 + 4];
            float4 bb = *(const float4*)&Wst[k][tc*4];
            float av[8] = {a0.x,a0.y,a0.z,a0.w,a1.x,a1.y,a1.z,a1.w};
            float bv[4] = {bb.x,bb.y,bb.z,bb.w};
            #pragma unroll
            for (int i = 0; i < 8; i++)
                #pragma unroll
                for (int j = 0; j < 4; j++)
                    acc[i][j] += av[i] * bv[j];
        }
    }

    int c = c0 + tc * 4;
    int h = c >> 5;
    int dcol = c & 31;
    #pragma unroll
    for (int i = 0; i < 8; i++) {
        int r = r0 + tq * 8 + i;
        int b = r >> 11;
        int n = r & (NN - 1);
        *(float4*)&dst[(((size_t)(b*HH + h) * NN) + n) * DH + dcol] =
            make_float4(acc[i][0], acc[i][1], acc[i][2], acc[i][3]);
    }
}

// Output projection: grid (32, 4)
__global__ void __launch_bounds__(256) gemm_out(const float* __restrict__ Wo,
                         const float* __restrict__ bo,
                         float* __restrict__ out) {
    __shared__ float Ast[16][132];
    __shared__ float Wst[16][68];

    int t  = threadIdx.x;
    int tq = t >> 4;
    int tc = t & 15;
    int r0 = blockIdx.x * 128;
    int c0 = blockIdx.y * 64;

    float acc[8][4];
    #pragma unroll
    for (int i = 0; i < 8; i++)
        #pragma unroll
        for (int j = 0; j < 4; j++) acc[i][j] = 0.f;

    for (int k0 = 0; k0 < DD; k0 += 16) {
        __syncthreads();
        #pragma unroll
        for (int rep = 0; rep < 2; rep++) {
            int idx = t + rep * 256;
            int row = idx >> 2;
            int kc  = (idx & 3) * 4;
            float4 a = *(const float4*)&g_attnout[(size_t)(r0 + row) * DD + k0 + kc];
            Ast[kc+0][row] = a.x; Ast[kc+1][row] = a.y;
            Ast[kc+2][row] = a.z; Ast[kc+3][row] = a.w;
        }
        {
            int idx = t;
            int col = idx >> 2;
            int kc  = (idx & 3) * 4;
            float4 w = *(const float4*)&Wo[(size_t)(c0 + col) * DD + k0 + kc];
            Wst[kc+0][col] = w.x; Wst[kc+1][col] = w.y;
            Wst[kc+2][col] = w.z; Wst[kc+3][col] = w.w;
        }
        __syncthreads();

        #pragma unroll
        for (int k = 0; k < 16; k++) {
            float4 a0 = *(const float4*)&Ast[k][tq*8];
            float4 a1 = *(const float4*)&Ast[k][tq*8 + 4];
            float4 bb = *(const float4*)&Wst[k][tc*4];
            float av[8] = {a0.x,a0.y,a0.z,a0.w,a1.x,a1.y,a1.z,a1.w};
            float bv[4] = {bb.x,bb.y,bb.z,bb.w};
            #pragma unroll
            for (int i = 0; i < 8; i++)
                #pragma unroll
                for (int j = 0; j < 4; j++)
                    acc[i][j] += av[i] * bv[j];
        }
    }

    float4 bv4 = *(const float4*)&bo[c0 + tc*4];
    #pragma unroll
    for (int i = 0; i < 8; i++) {
        int r = r0 + tq * 8 + i;
        *(float4*)&out[(size_t)r * DD + c0 + tc*4] =
            make_float4(acc[i][0] + bv4.x, acc[i][1] + bv4.y,
                        acc[i][2] + bv4.z, acc[i][3] + bv4.w);
    }
}

// ---------------------------------------------------------------------------
// Attention, split-K over 2 key halves.
// grid (NN/64, HH, BB*2), 256 threads. 64 queries per block, 64-key tiles.
// Score phase: thread (tq=t>>4, tk=t&15) computes 4q x 4k; PV phase: thread
// (tq, td=(t&15)>>1, ks2=t&1) computes 4q x 4d over half the keys.
// ---------------------------------------------------------------------------
__global__ void __launch_bounds__(256) attn_kernel(const float* __restrict__ adj) {
    __shared__ float Qst[32][68];   // transposed [d][q]
    __shared__ float Kst[32][68];   // transposed [d][k]
    __shared__ float Vs[64][36];    // [m][d]
    __shared__ float Pt[64][68];    // transposed [m][q], xor-swizzled cols

    int t  = threadIdx.x;
    int zb = blockIdx.z;
    int b  = zb >> 1;
    int kh = zb & 1;
    int h  = blockIdx.y;
    int q0 = blockIdx.x * 64;

    const size_t headoff = (size_t)(b*HH + h) * NN * DH;
    const float* Qg = g_Q + headoff;
    const float* Kg = g_K + headoff;
    const float* Vg = g_V + headoff;

    int tq  = t >> 4;
    int tk  = t & 15;
    int td  = (t & 15) >> 1;
    int ks2 = t & 1;

    // stage Q transposed (once)
    for (int idx = t; idx < 512; idx += 256) {
        int q  = idx >> 3;
        int dc = (idx & 7) * 4;
        float4 v = *(const float4*)&Qg[(size_t)(q0 + q) * DH + dc];
        Qst[dc+0][q] = v.x; Qst[dc+1][q] = v.y;
        Qst[dc+2][q] = v.z; Qst[dc+3][q] = v.w;
    }

    float o[4][4], rmax[4], rsum[4];
    #pragma unroll
    for (int i = 0; i < 4; i++) {
        rmax[i] = -1e30f; rsum[i] = 0.f;
        #pragma unroll
        for (int dd = 0; dd < 4; dd++) o[i][dd] = 0.f;
    }
    const float scale = 0.17677669529663688f;  // 1/sqrt(32)
    const int m_base = kh * (NN/2);

    for (int mt = 0; mt < NN/2; mt += 64) {
        int m0 = m_base + mt;
        __syncthreads();
        // stage K (transposed) and V (natural)
        for (int idx = t; idx < 512; idx += 256) {
            int r  = idx >> 3;
            int dc = (idx & 7) * 4;
            float4 kv = *(const float4*)&Kg[(size_t)(m0 + r) * DH + dc];
            Kst[dc+0][r] = kv.x; Kst[dc+1][r] = kv.y;
            Kst[dc+2][r] = kv.z; Kst[dc+3][r] = kv.w;
            float4 vv = *(const float4*)&Vg[(size_t)(m0 + r) * DH + dc];
            *(float4*)&Vs[r][dc] = vv;
        }
        // adjacency straight to registers (L2-resident)
        float am[4][4];
        #pragma unroll
        for (int i = 0; i < 4; i++) {
            float4 a = *(const float4*)&adj[((size_t)b*NN + (q0 + tq*4 + i)) * NN + m0 + tk*4];
            am[i][0]=a.x; am[i][1]=a.y; am[i][2]=a.z; am[i][3]=a.w;
        }
        __syncthreads();

        // scores 4x4
        float s[4][4];
        #pragma unroll
        for (int i = 0; i < 4; i++)
            #pragma unroll
            for (int j = 0; j < 4; j++) s[i][j] = 0.f;
        #pragma unroll
        for (int d = 0; d < 32; d++) {
            float4 qv = *(const float4*)&Qst[d][tq*4];
            float4 kv = *(const float4*)&Kst[d][tk*4];
            float qa[4] = {qv.x,qv.y,qv.z,qv.w};
            float ka[4] = {kv.x,kv.y,kv.z,kv.w};
            #pragma unroll
            for (int i = 0; i < 4; i++)
                #pragma unroll
                for (int j = 0; j < 4; j++)
                    s[i][j] += qa[i] * ka[j];
        }

        // masked online softmax (row reductions over the 16 tk-lanes)
        #pragma unroll
        for (int i = 0; i < 4; i++) {
            float mx = -3.0e38f;
            #pragma unroll
            for (int j = 0; j < 4; j++) {
                s[i][j] = (am[i][j] == 0.0f) ? -3.0e38f : s[i][j] * scale;
                mx = fmaxf(mx, s[i][j]);
            }
            mx = fmaxf(mx, __shfl_xor_sync(0xffffffffu, mx, 1));
            mx = fmaxf(mx, __shfl_xor_sync(0xffffffffu, mx, 2));
            mx = fmaxf(mx, __shfl_xor_sync(0xffffffffu, mx, 4));
            mx = fmaxf(mx, __shfl_xor_sync(0xffffffffu, mx, 8));
            float nm = fmaxf(rmax[i], mx);
            float corr = __expf(rmax[i] - nm);
            rmax[i] = nm;
            float ls = 0.f;
            #pragma unroll
            for (int j = 0; j < 4; j++) {
                s[i][j] = __expf(s[i][j] - nm);
                ls += s[i][j];
            }
            ls += __shfl_xor_sync(0xffffffffu, ls, 1);
            ls += __shfl_xor_sync(0xffffffffu, ls, 2);
            ls += __shfl_xor_sync(0xffffffffu, ls, 4);
            ls += __shfl_xor_sync(0xffffffffu, ls, 8);
            rsum[i] = rsum[i] * corr + ls;
            #pragma unroll
            for (int dd = 0; dd < 4; dd++) o[i][dd] *= corr;
        }

        // write P transposed + swizzled
        #pragma unroll
        for (int j = 0; j < 4; j++) {
            int m = tk*4 + j;
            int col = (tq*4) ^ ((( m >> 2) & 7) * 4);
            *(float4*)&Pt[m][col] = make_float4(s[0][j], s[1][j], s[2][j], s[3][j]);
        }
        __syncthreads();

        // PV 4x4 over half the keys (ks2 split)
        #pragma unroll
        for (int mm = 0; mm < 32; mm++) {
            int m = ks2*32 + mm;
            int col = (tq*4) ^ (((m >> 2) & 7) * 4);
            float4 p = *(const float4*)&Pt[m][col];
            float4 v = *(const float4*)&Vs[m][td*4];
            float pa[4] = {p.x,p.y,p.z,p.w};
            float va[4] = {v.x,v.y,v.z,v.w};
            #pragma unroll
            for (int i = 0; i < 4; i++)
                #pragma unroll
                for (int dd = 0; dd < 4; dd++)
                    o[i][dd] += pa[i] * va[dd];
        }
    }

    // fold the 2-way key split within lane pairs
    #pragma unroll
    for (int i = 0; i < 4; i++)
        #pragma unroll
        for (int dd = 0; dd < 4; dd++)
            o[i][dd] += __shfl_xor_sync(0xffffffffu, o[i][dd], 1);

    if (ks2 == 0) {
        int rowb = (b*HH + h)*NN + q0 + tq*4;
        #pragma unroll
        for (int i = 0; i < 4; i++) {
            size_t row = (size_t)(kh*R_ROWS + rowb + i);
            *(float4*)&g_po[row * DH + td*4] =
                make_float4(o[i][0], o[i][1], o[i][2], o[i][3]);
            if (td == 0) {
                g_pm[row*2 + 0] = rmax[i];
                g_pm[row*2 + 1] = rsum[i];
            }
        }
    }
}

// ---------------------------------------------------------------------------
// LSE combine of the two key-half partials -> concat-head layout.
// ---------------------------------------------------------------------------
__global__ void combine_kernel() {
    int idx = blockIdx.x * blockDim.x + threadIdx.x;   // 0..R_ROWS*8-1
    if (idx >= R_ROWS * 8) return;
    int row = idx >> 3;
    int dc  = (idx & 7) * 4;

    float m0 = g_pm[(size_t)row*2 + 0];
    float l0 = g_pm[(size_t)row*2 + 1];
    float m1 = g_pm[((size_t)R_ROWS + row)*2 + 0];
    float l1 = g_pm[((size_t)R_ROWS + row)*2 + 1];
    float M  = fmaxf(m0, m1);
    float w0 = __expf(m0 - M);
    float w1 = __expf(m1 - M);
    float inv = 1.0f / (l0*w0 + l1*w1);

    float4 o0 = *(const float4*)&g_po[(size_t)row * DH + dc];
    float4 o1 = *(const float4*)&g_po[((size_t)R_ROWS + row) * DH + dc];
    float4 r;
    r.x = (o0.x*w0 + o1.x*w1) * inv;
    r.y = (o0.y*w0 + o1.y*w1) * inv;
    r.z = (o0.z*w0 + o1.z*w1) * inv;
    r.w = (o0.w*w0 + o1.w*w1) * inv;

    int q  = row & (NN - 1);
    int t2 = row >> 11;
    int hh = t2 & (HH - 1);
    int bb = t2 >> 3;
    *(float4*)&g_attnout[((size_t)(bb*NN + q)) * DD + hh*DH + dc] = r;
}

extern "C" void kernel_launch(void* const* d_in, const int* in_sizes, int n_in,
                              void* d_out, int out_size) {
    const float* x   = (const float*)d_in[0];
    const float* adj = (const float*)d_in[1];
    const float* Wq  = (const float*)d_in[2];
    const float* Wk  = (const float*)d_in[3];
    const float* Wv  = (const float*)d_in[4];
    const float* Wo  = (const float*)d_in[5];
    const float* bo  = (const float*)d_in[6];
    float* out = (float*)d_out;

    gemm_qkv<<<dim3(32, 4, 3), 256>>>(x, Wq, Wk, Wv);
    attn_kernel<<<dim3(NN/64, HH, BB*2), 256>>>(adj);
    combine_kernel<<<(R_ROWS*8 + 255)/256, 256>>>();
    gemm_out<<<dim3(32, 4), 256>>>(Wo, bo, out);
}

// round 7
// speedup vs baseline: 3.8631x; 2.1674x over previous
#include <cuda_runtime.h>
#include <math.h>

#define BB 2
#define NN 2048
#define DD 256
#define HH 8
#define DH 32
#define R_ROWS (BB*HH*NN)
#define SPLIT 8

// Scratch (allocation-free rule: __device__ globals)
__device__ float g_Q[BB*HH*NN*DH];
__device__ float g_K[BB*HH*NN*DH];
__device__ float g_V[BB*HH*NN*DH];
__device__ unsigned g_adjbits[BB*NN*(NN/32)];
__device__ float g_po[SPLIT * R_ROWS * DH];   // unnormalized partial outputs
__device__ float g_pm[SPLIT * R_ROWS * 2];    // per-row (max, sum) per split (base-2 domain)
__device__ float g_attnout[BB*NN*DD];

// log2(e)/sqrt(32)
#define SCALE2 0.25503486f

// ---------------------------------------------------------------------------
// helpers
// ---------------------------------------------------------------------------
static __device__ __forceinline__ unsigned tf32u(float x) {
    unsigned u;
    asm("cvt.rna.tf32.f32 %0, %1;" : "=r"(u) : "f"(x));
    return u;
}
static __device__ __forceinline__ float tf32f(float x) {
    return __uint_as_float(tf32u(x));
}
static __device__ __forceinline__ float ex2f(float x) {
    float y;
    asm("ex2.approx.f32 %0, %1;" : "=f"(y) : "f"(x));
    return y;
}
static __device__ __forceinline__ void mma16n8k8(
    float& c0, float& c1, float& c2, float& c3,
    unsigned a0, unsigned a1, unsigned a2, unsigned a3,
    unsigned b0, unsigned b1)
{
    asm volatile(
        "mma.sync.aligned.m16n8k8.row.col.f32.tf32.tf32.f32 "
        "{%0,%1,%2,%3}, {%4,%5,%6,%7}, {%8,%9}, {%0,%1,%2,%3};"
        : "+f"(c0), "+f"(c1), "+f"(c2), "+f"(c3)
        : "r"(a0), "r"(a1), "r"(a2), "r"(a3), "r"(b0), "r"(b1));
}

// ---------------------------------------------------------------------------
// adjacency -> bitmask.  grid = BB*NN/8 blocks, 256 thr (8 warps, 1 row each)
// ---------------------------------------------------------------------------
__global__ void __launch_bounds__(256) adj2bits(const float* __restrict__ adj) {
    int row  = blockIdx.x * 8 + (threadIdx.x >> 5);
    int lane = threadIdx.x & 31;
    const float* arow = adj + (size_t)row * NN;
    unsigned* dst = g_adjbits + (size_t)row * (NN/32);
    #pragma unroll 4
    for (int w = 0; w < NN/32; w++) {
        float v = arow[w * 32 + lane];
        unsigned m = __ballot_sync(0xffffffffu, v != 0.0f);
        if (lane == 0) dst[w] = m;
    }
}

// ---------------------------------------------------------------------------
// QKV projection GEMM (fp32): 128x64 tiles. grid (32, 4, 3), 256 thr.
// ---------------------------------------------------------------------------
__global__ void __launch_bounds__(256) gemm_qkv(const float* __restrict__ x,
                         const float* __restrict__ Wq,
                         const float* __restrict__ Wk,
                         const float* __restrict__ Wv) {
    const float* W;
    float* dst;
    int z = blockIdx.z;
    if (z == 0)      { W = Wq; dst = g_Q; }
    else if (z == 1) { W = Wk; dst = g_K; }
    else             { W = Wv; dst = g_V; }

    __shared__ float Ast[16][132];
    __shared__ float Wst[16][68];

    int t  = threadIdx.x;
    int tq = t >> 4;
    int tc = t & 15;
    int r0 = blockIdx.x * 128;
    int c0 = blockIdx.y * 64;

    float acc[8][4];
    #pragma unroll
    for (int i = 0; i < 8; i++)
        #pragma unroll
        for (int j = 0; j < 4; j++) acc[i][j] = 0.f;

    for (int k0 = 0; k0 < DD; k0 += 16) {
        __syncthreads();
        #pragma unroll
        for (int rep = 0; rep < 2; rep++) {
            int idx = t + rep * 256;
            int row = idx >> 2;
            int kc  = (idx & 3) * 4;
            float4 a = *(const float4*)&x[(size_t)(r0 + row) * DD + k0 + kc];
            Ast[kc+0][row] = a.x; Ast[kc+1][row] = a.y;
            Ast[kc+2][row] = a.z; Ast[kc+3][row] = a.w;
        }
        {
            int col = t >> 2;
            int kc  = (t & 3) * 4;
            float4 w = *(const float4*)&W[(size_t)(c0 + col) * DD + k0 + kc];
            Wst[kc+0][col] = w.x; Wst[kc+1][col] = w.y;
            Wst[kc+2][col] = w.z; Wst[kc+3][col] = w.w;
        }
        __syncthreads();

        #pragma unroll
        for (int k = 0; k < 16; k++) {
            float4 a0 = *(const float4*)&Ast[k][tq*8];
            float4 a1 = *(const float4*)&Ast[k][tq*8 + 4];
            float4 bb = *(const float4*)&Wst[k][tc*4];
            float av[8] = {a0.x,a0.y,a0.z,a0.w,a1.x,a1.y,a1.z,a1.w};
            float bv[4] = {bb.x,bb.y,bb.z,bb.w};
            #pragma unroll
            for (int i = 0; i < 8; i++)
                #pragma unroll
                for (int j = 0; j < 4; j++)
                    acc[i][j] += av[i] * bv[j];
        }
    }

    int c = c0 + tc * 4;
    int h = c >> 5;
    int dcol = c & 31;
    #pragma unroll
    for (int i = 0; i < 8; i++) {
        int r = r0 + tq * 8 + i;
        int b = r >> 11;
        int n = r & (NN - 1);
        *(float4*)&dst[(((size_t)(b*HH + h) * NN) + n) * DH + dcol] =
            make_float4(acc[i][0], acc[i][1], acc[i][2], acc[i][3]);
    }
}

// ---------------------------------------------------------------------------
// Attention: tf32 mma.sync flash kernel, split-K over 8 key slices.
// grid (NN/128, HH, BB*SPLIT), 256 thr (8 warps, each owns 16 q-rows).
// smem (dynamic): Ks[64][36] | Vs[64][40] | Pt[8][16][76]   = 58368 B
// ---------------------------------------------------------------------------
#define ATTN_SMEM_FLOATS (2304 + 2560 + 9728)

__global__ void __launch_bounds__(256, 2) attn_kernel() {
    extern __shared__ float sm[];
    float* Ks = sm;                 // [64][36] tf32
    float* Vs = sm + 2304;          // [64][40] tf32
    float* Pt = sm + 4864;          // [8 warps][16][76] tf32

    int t    = threadIdx.x;
    int w    = t >> 5;
    int lane = t & 31;
    int lq   = lane & 3;   // thread-in-group
    int lg   = lane >> 2;  // group id (row / key-col selector)

    int zb = blockIdx.z;
    int b  = zb >> 3;
    int sp = zb & 7;
    int h  = blockIdx.y;
    int q0 = blockIdx.x * 128;

    const size_t headoff = (size_t)(b*HH + h) * NN * DH;
    const float* Qg = g_Q + headoff;
    const float* Kg = g_K + headoff;
    const float* Vg = g_V + headoff;

    int qrow = q0 + w*16 + lg;            // this thread's row pair: qrow, qrow+8

    // Q fragments (A of QK mma), loaded once: aq[kstep][0..3]
    unsigned aq[4][4];
    #pragma unroll
    for (int ks = 0; ks < 4; ks++) {
        aq[ks][0] = tf32u(Qg[(size_t)qrow     * DH + ks*8 + lq]);
        aq[ks][1] = tf32u(Qg[(size_t)(qrow+8) * DH + ks*8 + lq]);
        aq[ks][2] = tf32u(Qg[(size_t)qrow     * DH + ks*8 + lq + 4]);
        aq[ks][3] = tf32u(Qg[(size_t)(qrow+8) * DH + ks*8 + lq + 4]);
    }

    const unsigned* abr0 = g_adjbits + ((size_t)b*NN + qrow) * (NN/32);
    const unsigned* abr1 = abr0 + 8 * (NN/32);

    float co[4][4];                     // PV accumulators (4 d-tiles)
    #pragma unroll
    for (int i = 0; i < 4; i++)
        #pragma unroll
        for (int j = 0; j < 4; j++) co[i][j] = 0.f;
    float rmax0 = -3.0e38f, rmax1 = -3.0e38f, rsum0 = 0.f, rsum1 = 0.f;

    const int m_base = sp * (NN / SPLIT);
    float* Ptw = Pt + w * 1216;         // 16*76

    for (int mt = 0; mt < NN/SPLIT; mt += 64) {
        int m0 = m_base + mt;
        __syncthreads();
        // stage K, V (tf32-rounded)
        #pragma unroll
        for (int rep = 0; rep < 2; rep++) {
            int idx = t + rep * 256;
            int r   = idx >> 3;
            int dc  = (idx & 7) * 4;
            float4 kv = *(const float4*)&Kg[(size_t)(m0 + r) * DH + dc];
            Ks[r*36 + dc+0] = tf32f(kv.x); Ks[r*36 + dc+1] = tf32f(kv.y);
            Ks[r*36 + dc+2] = tf32f(kv.z); Ks[r*36 + dc+3] = tf32f(kv.w);
            float4 vv = *(const float4*)&Vg[(size_t)(m0 + r) * DH + dc];
            Vs[r*40 + dc+0] = tf32f(vv.x); Vs[r*40 + dc+1] = tf32f(vv.y);
            Vs[r*40 + dc+2] = tf32f(vv.z); Vs[r*40 + dc+3] = tf32f(vv.w);
        }
        uint2 wr0 = *(const uint2*)&abr0[m0 >> 5];
        uint2 wr1 = *(const uint2*)&abr1[m0 >> 5];
        __syncthreads();

        // ---- QK^T: 8 n-tiles x 4 k-steps ----
        float cs[8][4];
        #pragma unroll
        for (int nt = 0; nt < 8; nt++) {
            cs[nt][0] = cs[nt][1] = cs[nt][2] = cs[nt][3] = 0.f;
            #pragma unroll
            for (int ks = 0; ks < 4; ks++) {
                unsigned b0 = __float_as_uint(Ks[(nt*8 + lg)*36 + ks*8 + lq]);
                unsigned b1 = __float_as_uint(Ks[(nt*8 + lg)*36 + ks*8 + lq + 4]);
                mma16n8k8(cs[nt][0], cs[nt][1], cs[nt][2], cs[nt][3],
                          aq[ks][0], aq[ks][1], aq[ks][2], aq[ks][3], b0, b1);
            }
        }

        // ---- mask + scale (base-2 domain), row maxes ----
        float mx0 = -3.0e38f, mx1 = -3.0e38f;
        #pragma unroll
        for (int nt = 0; nt < 8; nt++) {
            unsigned wa = (nt < 4) ? wr0.x : wr0.y;
            unsigned wb = (nt < 4) ? wr1.x : wr1.y;
            int sh = (nt & 3)*8 + 2*lq;
            cs[nt][0] = ((wa >> sh)     & 1u) ? cs[nt][0]*SCALE2 : -3.0e38f;
            cs[nt][1] = ((wa >> (sh+1)) & 1u) ? cs[nt][1]*SCALE2 : -3.0e38f;
            cs[nt][2] = ((wb >> sh)     & 1u) ? cs[nt][2]*SCALE2 : -3.0e38f;
            cs[nt][3] = ((wb >> (sh+1)) & 1u) ? cs[nt][3]*SCALE2 : -3.0e38f;
            mx0 = fmaxf(mx0, fmaxf(cs[nt][0], cs[nt][1]));
            mx1 = fmaxf(mx1, fmaxf(cs[nt][2], cs[nt][3]));
        }
        mx0 = fmaxf(mx0, __shfl_xor_sync(0xffffffffu, mx0, 1));
        mx0 = fmaxf(mx0, __shfl_xor_sync(0xffffffffu, mx0, 2));
        mx1 = fmaxf(mx1, __shfl_xor_sync(0xffffffffu, mx1, 1));
        mx1 = fmaxf(mx1, __shfl_xor_sync(0xffffffffu, mx1, 2));

        float nm0 = fmaxf(rmax0, mx0);
        float nm1 = fmaxf(rmax1, mx1);
        float corr0 = ex2f(rmax0 - nm0);
        float corr1 = ex2f(rmax1 - nm1);
        rmax0 = nm0; rmax1 = nm1;

        float ls0 = 0.f, ls1 = 0.f;
        #pragma unroll
        for (int nt = 0; nt < 8; nt++) {
            cs[nt][0] = ex2f(cs[nt][0] - nm0);
            cs[nt][1] = ex2f(cs[nt][1] - nm0);
            cs[nt][2] = ex2f(cs[nt][2] - nm1);
            cs[nt][3] = ex2f(cs[nt][3] - nm1);
            ls0 += cs[nt][0] + cs[nt][1];
            ls1 += cs[nt][2] + cs[nt][3];
        }
        ls0 += __shfl_xor_sync(0xffffffffu, ls0, 1);
        ls0 += __shfl_xor_sync(0xffffffffu, ls0, 2);
        ls1 += __shfl_xor_sync(0xffffffffu, ls1, 1);
        ls1 += __shfl_xor_sync(0xffffffffu, ls1, 2);
        rsum0 = rsum0 * corr0 + ls0;
        rsum1 = rsum1 * corr1 + ls1;
        #pragma unroll
        for (int i = 0; i < 4; i++) {
            co[i][0] *= corr0; co[i][1] *= corr0;
            co[i][2] *= corr1; co[i][3] *= corr1;
        }

        // ---- P -> per-warp smem (tf32), C-layout to A-layout relay ----
        #pragma unroll
        for (int nt = 0; nt < 8; nt++) {
            float2 p0 = make_float2(tf32f(cs[nt][0]), tf32f(cs[nt][1]));
            float2 p1 = make_float2(tf32f(cs[nt][2]), tf32f(cs[nt][3]));
            *(float2*)&Ptw[lg*76      + nt*8 + 2*lq] = p0;
            *(float2*)&Ptw[(lg+8)*76  + nt*8 + 2*lq] = p1;
        }
        __syncwarp();

        // ---- PV: 8 k-steps x 4 d-tiles ----
        #pragma unroll
        for (int ks = 0; ks < 8; ks++) {
            unsigned a0 = __float_as_uint(Ptw[lg*76     + ks*8 + lq]);
            unsigned a1 = __float_as_uint(Ptw[(lg+8)*76 + ks*8 + lq]);
            unsigned a2 = __float_as_uint(Ptw[lg*76     + ks*8 + lq + 4]);
            unsigned a3 = __float_as_uint(Ptw[(lg+8)*76 + ks*8 + lq + 4]);
            #pragma unroll
            for (int ntd = 0; ntd < 4; ntd++) {
                unsigned b0 = __float_as_uint(Vs[(ks*8 + lq)*40     + ntd*8 + lg]);
                unsigned b1 = __float_as_uint(Vs[(ks*8 + lq + 4)*40 + ntd*8 + lg]);
                mma16n8k8(co[ntd][0], co[ntd][1], co[ntd][2], co[ntd][3],
                          a0, a1, a2, a3, b0, b1);
            }
        }
        __syncwarp();   // Pt reads done before next tile's writes
    }

    // ---- epilogue: unnormalized partials + (max, sum) ----
    size_t rowb  = (size_t)(b*HH + h) * NN + qrow;
    size_t base0 = ((size_t)sp * R_ROWS + rowb) * DH;
    size_t base1 = base0 + 8 * DH;
    #pragma unroll
    for (int ntd = 0; ntd < 4; ntd++) {
        *(float2*)&g_po[base0 + ntd*8 + 2*lq] = make_float2(co[ntd][0], co[ntd][1]);
        *(float2*)&g_po[base1 + ntd*8 + 2*lq] = make_float2(co[ntd][2], co[ntd][3]);
    }
    if (lq == 0) {
        size_t pr0 = ((size_t)sp * R_ROWS + rowb) * 2;
        size_t pr1 = pr0 + 8 * 2;
        g_pm[pr0 + 0] = rmax0; g_pm[pr0 + 1] = rsum0;
        g_pm[pr1 + 0] = rmax1; g_pm[pr1 + 1] = rsum1;
    }
}

// ---------------------------------------------------------------------------
// LSE combine of SPLIT partials -> concat-head layout (base-2 domain).
// ---------------------------------------------------------------------------
__global__ void __launch_bounds__(256) combine_kernel() {
    int idx = blockIdx.x * blockDim.x + threadIdx.x;   // 0..R_ROWS*8-1
    if (idx >= R_ROWS * 8) return;
    int row = idx >> 3;
    int dc  = (idx & 7) * 4;

    float m[SPLIT], l[SPLIT];
    float M = -3.0e38f;
    #pragma unroll
    for (int s = 0; s < SPLIT; s++) {
        m[s] = g_pm[((size_t)s * R_ROWS + row)*2 + 0];
        l[s] = g_pm[((size_t)s * R_ROWS + row)*2 + 1];
        M = fmaxf(M, m[s]);
    }
    float denom = 0.f;
    float4 acc = make_float4(0.f, 0.f, 0.f, 0.f);
    #pragma unroll
    for (int s = 0; s < SPLIT; s++) {
        float wgt = ex2f(m[s] - M);
        denom += l[s] * wgt;
        float4 o = *(const float4*)&g_po[((size_t)s * R_ROWS + row) * DH + dc];
        acc.x += o.x * wgt; acc.y += o.y * wgt;
        acc.z += o.z * wgt; acc.w += o.w * wgt;
    }
    float inv = 1.0f / denom;

    int q  = row & (NN - 1);
    int t2 = row >> 11;
    int hh = t2 & (HH - 1);
    int bb = t2 >> 3;
    *(float4*)&g_attnout[((size_t)(bb*NN + q)) * DD + hh*DH + dc] =
        make_float4(acc.x*inv, acc.y*inv, acc.z*inv, acc.w*inv);
}

// ---------------------------------------------------------------------------
// Output projection (fp32): 64x64 tiles, grid (64, 4), 256 thr.
// ---------------------------------------------------------------------------
__global__ void __launch_bounds__(256) gemm_out(const float* __restrict__ Wo,
                         const float* __restrict__ bo,
                         float* __restrict__ out) {
    __shared__ float Ast[16][68];
    __shared__ float Wst[16][68];

    int t  = threadIdx.x;
    int tm = t >> 4;
    int tn = t & 15;
    int r0 = blockIdx.x * 64;
    int c0 = blockIdx.y * 64;

    float acc[4][4];
    #pragma unroll
    for (int i = 0; i < 4; i++)
        #pragma unroll
        for (int j = 0; j < 4; j++) acc[i][j] = 0.f;

    int srow = t >> 2;
    int skc  = (t & 3) * 4;

    for (int k0 = 0; k0 < DD; k0 += 16) {
        __syncthreads();
        {
            float4 a = *(const float4*)&g_attnout[(size_t)(r0 + srow) * DD + k0 + skc];
            Ast[skc+0][srow] = a.x; Ast[skc+1][srow] = a.y;
            Ast[skc+2][srow] = a.z; Ast[skc+3][srow] = a.w;
            float4 ww = *(const float4*)&Wo[(size_t)(c0 + srow) * DD + k0 + skc];
            Wst[skc+0][srow] = ww.x; Wst[skc+1][srow] = ww.y;
            Wst[skc+2][srow] = ww.z; Wst[skc+3][srow] = ww.w;
        }
        __syncthreads();

        #pragma unroll
        for (int k = 0; k < 16; k++) {
            float4 a0 = *(const float4*)&Ast[k][tm*4];
            float4 b0 = *(const float4*)&Wst[k][tn*4];
            float av[4] = {a0.x, a0.y, a0.z, a0.w};
            float bv[4] = {b0.x, b0.y, b0.z, b0.w};
            #pragma unroll
            for (int i = 0; i < 4; i++)
                #pragma unroll
                for (int j = 0; j < 4; j++)
                    acc[i][j] += av[i] * bv[j];
        }
    }

    float4 bv4 = *(const float4*)&bo[c0 + tn*4];
    #pragma unroll
    for (int i = 0; i < 4; i++) {
        int r = r0 + tm*4 + i;
        *(float4*)&out[(size_t)r * DD + c0 + tn*4] =
            make_float4(acc[i][0] + bv4.x, acc[i][1] + bv4.y,
                        acc[i][2] + bv4.z, acc[i][3] + bv4.w);
    }
}

extern "C" void kernel_launch(void* const* d_in, const int* in_sizes, int n_in,
                              void* d_out, int out_size) {
    const float* x   = (const float*)d_in[0];
    const float* adj = (const float*)d_in[1];
    const float* Wq  = (const float*)d_in[2];
    const float* Wk  = (const float*)d_in[3];
    const float* Wv  = (const float*)d_in[4];
    const float* Wo  = (const float*)d_in[5];
    const float* bo  = (const float*)d_in[6];
    float* out = (float*)d_out;

    static int smem_set = 0;
    if (!smem_set) {
        cudaFuncSetAttribute(attn_kernel,
                             cudaFuncAttributeMaxDynamicSharedMemorySize,
                             ATTN_SMEM_FLOATS * 4);
        smem_set = 1;
    }

    adj2bits<<<BB*NN/8, 256>>>(adj);
    gemm_qkv<<<dim3(32, 4, 3), 256>>>(x, Wq, Wk, Wv);
    attn_kernel<<<dim3(NN/128, HH, BB*SPLIT), 256, ATTN_SMEM_FLOATS * 4>>>();
    combine_kernel<<<(R_ROWS*8 + 255)/256, 256>>>();
    gemm_out<<<dim3(64, 4), 256>>>(Wo, bo, out);
}

// round 12
// speedup vs baseline: 4.2085x; 1.0894x over previous
#include <cuda_runtime.h>
#include <math.h>

#define BB 2
#define NN 2048
#define DD 256
#define HH 8
#define DH 32
#define R_ROWS (BB*HH*NN)
#define SPLIT 8

// Scratch (allocation-free rule: __device__ globals)
__device__ float g_Q[BB*HH*NN*DH];
__device__ float g_K[BB*HH*NN*DH];
__device__ float g_V[BB*HH*NN*DH];
__device__ unsigned g_adjbits[BB*NN*(NN/32)];
__device__ float g_po[SPLIT * R_ROWS * DH];   // unnormalized partial outputs
__device__ float g_pm[SPLIT * R_ROWS * 2];    // per-row (max, sum) per split (base-2 domain)
__device__ float g_attnout[BB*NN*DD];

// log2(e)/sqrt(32)
#define SCALE2 0.25503486f

// ---------------------------------------------------------------------------
// helpers
// ---------------------------------------------------------------------------
static __device__ __forceinline__ unsigned tf32u(float x) {
    unsigned u;
    asm("cvt.rna.tf32.f32 %0, %1;" : "=r"(u) : "f"(x));
    return u;
}
static __device__ __forceinline__ float tf32f(float x) {
    return __uint_as_float(tf32u(x));
}
static __device__ __forceinline__ float ex2f(float x) {
    float y;
    asm("ex2.approx.f32 %0, %1;" : "=f"(y) : "f"(x));
    return y;
}
static __device__ __forceinline__ void mma16n8k8(
    float& c0, float& c1, float& c2, float& c3,
    unsigned a0, unsigned a1, unsigned a2, unsigned a3,
    unsigned b0, unsigned b1)
{
    asm volatile(
        "mma.sync.aligned.m16n8k8.row.col.f32.tf32.tf32.f32 "
        "{%0,%1,%2,%3}, {%4,%5,%6,%7}, {%8,%9}, {%0,%1,%2,%3};"
        : "+f"(c0), "+f"(c1), "+f"(c2), "+f"(c3)
        : "r"(a0), "r"(a1), "r"(a2), "r"(a3), "r"(b0), "r"(b1));
}

// ---------------------------------------------------------------------------
// Fused prep kernel:
//   blocks [0, 512):   adjacency -> bitmask (DRAM-bound)
//   blocks [512, 896): QKV projection, 3xTF32 tensor GEMM (tensor-bound)
// 256 threads. 128x64 output tiles for the GEMM part, KC=16 k-chunks.
// ---------------------------------------------------------------------------
__global__ void __launch_bounds__(256, 3) prep_kernel(
        const float* __restrict__ x,
        const float* __restrict__ adj,
        const float* __restrict__ Wq,
        const float* __restrict__ Wk,
        const float* __restrict__ Wv) {
    __shared__ float Ahi[128*20];
    __shared__ float Alo[128*20];
    __shared__ float Whi[64*20];
    __shared__ float Wlo[64*20];

    int t = threadIdx.x;

    if (blockIdx.x < 512) {
        // ---- adj2bits ----
        int row  = blockIdx.x * 8 + (t >> 5);
        int lane = t & 31;
        const float* arow = adj + (size_t)row * NN;
        unsigned* dst = g_adjbits + (size_t)row * (NN/32);
        #pragma unroll 4
        for (int wj = 0; wj < NN/32; wj++) {
            float v = arow[wj * 32 + lane];
            unsigned m = __ballot_sync(0xffffffffu, v != 0.0f);
            if (lane == 0) dst[wj] = m;
        }
        return;
    }

    // ---- QKV tensor GEMM ----
    int bid = blockIdx.x - 512;          // 0..383
    int z   = bid >> 7;                  // matrix select
    int lb  = bid & 127;
    int r0  = (lb >> 2) * 128;
    int c0  = (lb & 3) * 64;

    const float* W;
    float* dst;
    if (z == 0)      { W = Wq; dst = g_Q; }
    else if (z == 1) { W = Wk; dst = g_K; }
    else             { W = Wv; dst = g_V; }

    int w    = t >> 5;
    int lane = t & 31;
    int lq   = lane & 3;
    int lg   = lane >> 2;
    int w16  = w * 16;

    float acc[8][4];
    #pragma unroll
    for (int i = 0; i < 8; i++)
        #pragma unroll
        for (int j = 0; j < 4; j++) acc[i][j] = 0.f;

    for (int k0 = 0; k0 < DD; k0 += 16) {
        __syncthreads();
        // stage A (x) slab 128x16, split into hi/lo tf32
        #pragma unroll
        for (int rep = 0; rep < 2; rep++) {
            int idx = t + rep * 256;
            int row = idx >> 2;
            int kc  = (idx & 3) * 4;
            float4 a = *(const float4*)&x[(size_t)(r0 + row) * DD + k0 + kc];
            float4 h, l;
            h.x = tf32f(a.x); l.x = tf32f(a.x - h.x);
            h.y = tf32f(a.y); l.y = tf32f(a.y - h.y);
            h.z = tf32f(a.z); l.z = tf32f(a.z - h.z);
            h.w = tf32f(a.w); l.w = tf32f(a.w - h.w);
            *(float4*)&Ahi[row*20 + kc] = h;
            *(float4*)&Alo[row*20 + kc] = l;
        }
        // stage W slab 64x16
        {
            int col = t >> 2;
            int kc  = (t & 3) * 4;
            float4 a = *(const float4*)&W[(size_t)(c0 + col) * DD + k0 + kc];
            float4 h, l;
            h.x = tf32f(a.x); l.x = tf32f(a.x - h.x);
            h.y = tf32f(a.y); l.y = tf32f(a.y - h.y);
            h.z = tf32f(a.z); l.z = tf32f(a.z - h.z);
            h.w = tf32f(a.w); l.w = tf32f(a.w - h.w);
            *(float4*)&Whi[col*20 + kc] = h;
            *(float4*)&Wlo[col*20 + kc] = l;
        }
        __syncthreads();

        #pragma unroll
        for (int ks8 = 0; ks8 < 16; ks8 += 8) {
            int ar0 = (w16 + lg)*20 + ks8 + lq;
            int ar1 = (w16 + lg + 8)*20 + ks8 + lq;
            unsigned ah0 = __float_as_uint(Ahi[ar0]);
            unsigned ah1 = __float_as_uint(Ahi[ar1]);
            unsigned ah2 = __float_as_uint(Ahi[ar0 + 4]);
            unsigned ah3 = __float_as_uint(Ahi[ar1 + 4]);
            unsigned al0 = __float_as_uint(Alo[ar0]);
            unsigned al1 = __float_as_uint(Alo[ar1]);
            unsigned al2 = __float_as_uint(Alo[ar0 + 4]);
            unsigned al3 = __float_as_uint(Alo[ar1 + 4]);
            #pragma unroll
            for (int nt = 0; nt < 8; nt++) {
                int br = (nt*8 + lg)*20 + ks8 + lq;
                unsigned bh0 = __float_as_uint(Whi[br]);
                unsigned bh1 = __float_as_uint(Whi[br + 4]);
                unsigned bl0 = __float_as_uint(Wlo[br]);
                unsigned bl1 = __float_as_uint(Wlo[br + 4]);
                mma16n8k8(acc[nt][0], acc[nt][1], acc[nt][2], acc[nt][3],
                          ah0, ah1, ah2, ah3, bh0, bh1);
                mma16n8k8(acc[nt][0], acc[nt][1], acc[nt][2], acc[nt][3],
                          ah0, ah1, ah2, ah3, bl0, bl1);
                mma16n8k8(acc[nt][0], acc[nt][1], acc[nt][2], acc[nt][3],
                          al0, al1, al2, al3, bh0, bh1);
            }
        }
    }

    // epilogue: scatter to [b][h][n][d]
    int r_a = r0 + w16 + lg;
    int r_b = r_a + 8;
    int ba = r_a >> 11, na = r_a & (NN-1);
    int bb2 = r_b >> 11, nb = r_b & (NN-1);
    #pragma unroll
    for (int nt = 0; nt < 8; nt++) {
        int c = c0 + nt*8 + 2*lq;
        int h = c >> 5;
        int d = c & 31;
        *(float2*)&dst[(((size_t)(ba*HH + h) * NN) + na) * DH + d] =
            make_float2(acc[nt][0], acc[nt][1]);
        *(float2*)&dst[(((size_t)(bb2*HH + h) * NN) + nb) * DH + d] =
            make_float2(acc[nt][2], acc[nt][3]);
    }
}

// ---------------------------------------------------------------------------
// Attention: tf32 mma.sync flash kernel, split-K over 8 key slices.
// grid (NN/128, HH, BB*SPLIT), 256 thr (8 warps, each owns 16 q-rows).
// P relayout C-frag -> A-frag done with warp shuffles (no smem P).
// static smem: Ks[64][36] + Vs[64][40] = 19456 B
// ---------------------------------------------------------------------------
__global__ void __launch_bounds__(256, 2) attn_kernel() {
    __shared__ float Ks[64*36];
    __shared__ float Vs[64*40];

    int t    = threadIdx.x;
    int w    = t >> 5;
    int lane = t & 31;
    int lq   = lane & 3;   // thread-in-group
    int lg   = lane >> 2;  // group id

    int zb = blockIdx.z;
    int b  = zb >> 3;
    int sp = zb & 7;
    int h  = blockIdx.y;
    int q0 = blockIdx.x * 128;

    const size_t headoff = (size_t)(b*HH + h) * NN * DH;
    const float* Qg = g_Q + headoff;
    const float* Kg = g_K + headoff;
    const float* Vg = g_V + headoff;

    int qrow = q0 + w*16 + lg;            // row pair: qrow, qrow+8

    // Q fragments, loaded once
    unsigned aq[4][4];
    #pragma unroll
    for (int ks = 0; ks < 4; ks++) {
        aq[ks][0] = tf32u(Qg[(size_t)qrow     * DH + ks*8 + lq]);
        aq[ks][1] = tf32u(Qg[(size_t)(qrow+8) * DH + ks*8 + lq]);
        aq[ks][2] = tf32u(Qg[(size_t)qrow     * DH + ks*8 + lq + 4]);
        aq[ks][3] = tf32u(Qg[(size_t)(qrow+8) * DH + ks*8 + lq + 4]);
    }

    const unsigned* abr0 = g_adjbits + ((size_t)b*NN + qrow) * (NN/32);
    const unsigned* abr1 = abr0 + 8 * (NN/32);

    float co[4][4];
    #pragma unroll
    for (int i = 0; i < 4; i++)
        #pragma unroll
        for (int j = 0; j < 4; j++) co[i][j] = 0.f;
    float rmax0 = -3.0e38f, rmax1 = -3.0e38f, rsum0 = 0.f, rsum1 = 0.f;

    const int m_base = sp * (NN / SPLIT);
    const int srcA = (lane & ~3) | (lq >> 1);   // shuffle source for P relayout
    const bool oddq = (lq & 1);

    for (int mt = 0; mt < NN/SPLIT; mt += 64) {
        int m0 = m_base + mt;
        __syncthreads();
        // stage K, V (tf32-rounded)
        #pragma unroll
        for (int rep = 0; rep < 2; rep++) {
            int idx = t + rep * 256;
            int r   = idx >> 3;
            int dc  = (idx & 7) * 4;
            float4 kv = *(const float4*)&Kg[(size_t)(m0 + r) * DH + dc];
            Ks[r*36 + dc+0] = tf32f(kv.x); Ks[r*36 + dc+1] = tf32f(kv.y);
            Ks[r*36 + dc+2] = tf32f(kv.z); Ks[r*36 + dc+3] = tf32f(kv.w);
            float4 vv = *(const float4*)&Vg[(size_t)(m0 + r) * DH + dc];
            Vs[r*40 + dc+0] = tf32f(vv.x); Vs[r*40 + dc+1] = tf32f(vv.y);
            Vs[r*40 + dc+2] = tf32f(vv.z); Vs[r*40 + dc+3] = tf32f(vv.w);
        }
        uint2 wr0 = *(const uint2*)&abr0[m0 >> 5];
        uint2 wr1 = *(const uint2*)&abr1[m0 >> 5];
        __syncthreads();

        // ---- QK^T: 8 n-tiles x 4 k-steps ----
        float cs[8][4];
        #pragma unroll
        for (int nt = 0; nt < 8; nt++) {
            cs[nt][0] = cs[nt][1] = cs[nt][2] = cs[nt][3] = 0.f;
            #pragma unroll
            for (int ks = 0; ks < 4; ks++) {
                unsigned b0 = __float_as_uint(Ks[(nt*8 + lg)*36 + ks*8 + lq]);
                unsigned b1 = __float_as_uint(Ks[(nt*8 + lg)*36 + ks*8 + lq + 4]);
                mma16n8k8(cs[nt][0], cs[nt][1], cs[nt][2], cs[nt][3],
                          aq[ks][0], aq[ks][1], aq[ks][2], aq[ks][3], b0, b1);
            }
        }

        // ---- mask + scale (base-2 domain), row maxes ----
        float mx0 = -3.0e38f, mx1 = -3.0e38f;
        #pragma unroll
        for (int nt = 0; nt < 8; nt++) {
            unsigned wa = (nt < 4) ? wr0.x : wr0.y;
            unsigned wb = (nt < 4) ? wr1.x : wr1.y;
            int sh = (nt & 3)*8 + 2*lq;
            cs[nt][0] = ((wa >> sh)     & 1u) ? cs[nt][0]*SCALE2 : -3.0e38f;
            cs[nt][1] = ((wa >> (sh+1)) & 1u) ? cs[nt][1]*SCALE2 : -3.0e38f;
            cs[nt][2] = ((wb >> sh)     & 1u) ? cs[nt][2]*SCALE2 : -3.0e38f;
            cs[nt][3] = ((wb >> (sh+1)) & 1u) ? cs[nt][3]*SCALE2 : -3.0e38f;
            mx0 = fmaxf(mx0, fmaxf(cs[nt][0], cs[nt][1]));
            mx1 = fmaxf(mx1, fmaxf(cs[nt][2], cs[nt][3]));
        }
        mx0 = fmaxf(mx0, __shfl_xor_sync(0xffffffffu, mx0, 1));
        mx0 = fmaxf(mx0, __shfl_xor_sync(0xffffffffu, mx0, 2));
        mx1 = fmaxf(mx1, __shfl_xor_sync(0xffffffffu, mx1, 1));
        mx1 = fmaxf(mx1, __shfl_xor_sync(0xffffffffu, mx1, 2));

        float nm0 = fmaxf(rmax0, mx0);
        float nm1 = fmaxf(rmax1, mx1);
        float corr0 = ex2f(rmax0 - nm0);
        float corr1 = ex2f(rmax1 - nm1);
        rmax0 = nm0; rmax1 = nm1;

        float ls0 = 0.f, ls1 = 0.f;
        #pragma unroll
        for (int nt = 0; nt < 8; nt++) {
            cs[nt][0] = ex2f(cs[nt][0] - nm0);
            cs[nt][1] = ex2f(cs[nt][1] - nm0);
            cs[nt][2] = ex2f(cs[nt][2] - nm1);
            cs[nt][3] = ex2f(cs[nt][3] - nm1);
            ls0 += cs[nt][0] + cs[nt][1];
            ls1 += cs[nt][2] + cs[nt][3];
        }
        ls0 += __shfl_xor_sync(0xffffffffu, ls0, 1);
        ls0 += __shfl_xor_sync(0xffffffffu, ls0, 2);
        ls1 += __shfl_xor_sync(0xffffffffu, ls1, 1);
        ls1 += __shfl_xor_sync(0xffffffffu, ls1, 2);
        rsum0 = rsum0 * corr0 + ls0;
        rsum1 = rsum1 * corr1 + ls1;
        #pragma unroll
        for (int i = 0; i < 4; i++) {
            co[i][0] *= corr0; co[i][1] *= corr0;
            co[i][2] *= corr1; co[i][3] *= corr1;
        }

        // ---- PV: C-frag -> A-frag via quad shuffles, then 8 k-steps x 4 d-tiles ----
        #pragma unroll
        for (int ks = 0; ks < 8; ks++) {
            float v00 = __shfl_sync(0xffffffffu, cs[ks][0], srcA);
            float v01 = __shfl_sync(0xffffffffu, cs[ks][1], srcA);
            float v10 = __shfl_sync(0xffffffffu, cs[ks][2], srcA);
            float v11 = __shfl_sync(0xffffffffu, cs[ks][3], srcA);
            float v20 = __shfl_sync(0xffffffffu, cs[ks][0], srcA + 2);
            float v21 = __shfl_sync(0xffffffffu, cs[ks][1], srcA + 2);
            float v30 = __shfl_sync(0xffffffffu, cs[ks][2], srcA + 2);
            float v31 = __shfl_sync(0xffffffffu, cs[ks][3], srcA + 2);
            unsigned a0 = tf32u(oddq ? v01 : v00);
            unsigned a1 = tf32u(oddq ? v11 : v10);
            unsigned a2 = tf32u(oddq ? v21 : v20);
            unsigned a3 = tf32u(oddq ? v31 : v30);
            #pragma unroll
            for (int ntd = 0; ntd < 4; ntd++) {
                unsigned b0 = __float_as_uint(Vs[(ks*8 + lq)*40     + ntd*8 + lg]);
                unsigned b1 = __float_as_uint(Vs[(ks*8 + lq + 4)*40 + ntd*8 + lg]);
                mma16n8k8(co[ntd][0], co[ntd][1], co[ntd][2], co[ntd][3],
                          a0, a1, a2, a3, b0, b1);
            }
        }
    }

    // ---- epilogue: unnormalized partials + (max, sum) ----
    size_t rowb  = (size_t)(b*HH + h) * NN + qrow;
    size_t base0 = ((size_t)sp * R_ROWS + rowb) * DH;
    size_t base1 = base0 + 8 * DH;
    #pragma unroll
    for (int ntd = 0; ntd < 4; ntd++) {
        *(float2*)&g_po[base0 + ntd*8 + 2*lq] = make_float2(co[ntd][0], co[ntd][1]);
        *(float2*)&g_po[base1 + ntd*8 + 2*lq] = make_float2(co[ntd][2], co[ntd][3]);
    }
    if (lq == 0) {
        size_t pr0 = ((size_t)sp * R_ROWS + rowb) * 2;
        size_t pr1 = pr0 + 8 * 2;
        g_pm[pr0 + 0] = rmax0; g_pm[pr0 + 1] = rsum0;
        g_pm[pr1 + 0] = rmax1; g_pm[pr1 + 1] = rsum1;
    }
}

// ---------------------------------------------------------------------------
// LSE combine of SPLIT partials -> concat-head layout (base-2 domain).
// ---------------------------------------------------------------------------
__global__ void __launch_bounds__(256) combine_kernel() {
    int idx = blockIdx.x * blockDim.x + threadIdx.x;   // 0..R_ROWS*8-1
    if (idx >= R_ROWS * 8) return;
    int row = idx >> 3;
    int dc  = (idx & 7) * 4;

    float m[SPLIT], l[SPLIT];
    float M = -3.0e38f;
    #pragma unroll
    for (int s = 0; s < SPLIT; s++) {
        m[s] = g_pm[((size_t)s * R_ROWS + row)*2 + 0];
        l[s] = g_pm[((size_t)s * R_ROWS + row)*2 + 1];
        M = fmaxf(M, m[s]);
    }
    float denom = 0.f;
    float4 acc = make_float4(0.f, 0.f, 0.f, 0.f);
    #pragma unroll
    for (int s = 0; s < SPLIT; s++) {
        float wgt = ex2f(m[s] - M);
        denom += l[s] * wgt;
        float4 o = *(const float4*)&g_po[((size_t)s * R_ROWS + row) * DH + dc];
        acc.x += o.x * wgt; acc.y += o.y * wgt;
        acc.z += o.z * wgt; acc.w += o.w * wgt;
    }
    float inv = 1.0f / denom;

    int q  = row & (NN - 1);
    int t2 = row >> 11;
    int hh = t2 & (HH - 1);
    int bb = t2 >> 3;
    *(float4*)&g_attnout[((size_t)(bb*NN + q)) * DD + hh*DH + dc] =
        make_float4(acc.x*inv, acc.y*inv, acc.z*inv, acc.w*inv);
}

// ---------------------------------------------------------------------------
// Output projection, 3xTF32 tensor GEMM. 128x64 tiles, grid (32, 4), 256 thr.
// ---------------------------------------------------------------------------
__global__ void __launch_bounds__(256, 3) gemm_out(const float* __restrict__ Wo,
                         const float* __restrict__ bo,
                         float* __restrict__ out) {
    __shared__ float Ahi[128*20];
    __shared__ float Alo[128*20];
    __shared__ float Whi[64*20];
    __shared__ float Wlo[64*20];

    int t    = threadIdx.x;
    int w    = t >> 5;
    int lane = t & 31;
    int lq   = lane & 3;
    int lg   = lane >> 2;
    int w16  = w * 16;
    int r0   = blockIdx.x * 128;
    int c0   = blockIdx.y * 64;

    float acc[8][4];
    #pragma unroll
    for (int i = 0; i < 8; i++)
        #pragma unroll
        for (int j = 0; j < 4; j++) acc[i][j] = 0.f;

    for (int k0 = 0; k0 < DD; k0 += 16) {
        __syncthreads();
        #pragma unroll
        for (int rep = 0; rep < 2; rep++) {
            int idx = t + rep * 256;
            int row = idx >> 2;
            int kc  = (idx & 3) * 4;
            float4 a = *(const float4*)&g_attnout[(size_t)(r0 + row) * DD + k0 + kc];
            float4 h, l;
            h.x = tf32f(a.x); l.x = tf32f(a.x - h.x);
            h.y = tf32f(a.y); l.y = tf32f(a.y - h.y);
            h.z = tf32f(a.z); l.z = tf32f(a.z - h.z);
            h.w = tf32f(a.w); l.w = tf32f(a.w - h.w);
            *(float4*)&Ahi[row*20 + kc] = h;
            *(float4*)&Alo[row*20 + kc] = l;
        }
        {
            int col = t >> 2;
            int kc  = (t & 3) * 4;
            float4 a = *(const float4*)&Wo[(size_t)(c0 + col) * DD + k0 + kc];
            float4 h, l;
            h.x = tf32f(a.x); l.x = tf32f(a.x - h.x);
            h.y = tf32f(a.y); l.y = tf32f(a.y - h.y);
            h.z = tf32f(a.z); l.z = tf32f(a.z - h.z);
            h.w = tf32f(a.w); l.w = tf32f(a.w - h.w);
            *(float4*)&Whi[col*20 + kc] = h;
            *(float4*)&Wlo[col*20 + kc] = l;
        }
        __syncthreads();

        #pragma unroll
        for (int ks8 = 0; ks8 < 16; ks8 += 8) {
            int ar0 = (w16 + lg)*20 + ks8 + lq;
            int ar1 = (w16 + lg + 8)*20 + ks8 + lq;
            unsigned ah0 = __float_as_uint(Ahi[ar0]);
            unsigned ah1 = __float_as_uint(Ahi[ar1]);
            unsigned ah2 = __float_as_uint(Ahi[ar0 + 4]);
            unsigned ah3 = __float_as_uint(Ahi[ar1 + 4]);
            unsigned al0 = __float_as_uint(Alo[ar0]);
            unsigned al1 = __float_as_uint(Alo[ar1]);
            unsigned al2 = __float_as_uint(Alo[ar0 + 4]);
            unsigned al3 = __float_as_uint(Alo[ar1 + 4]);
            #pragma unroll
            for (int nt = 0; nt < 8; nt++) {
                int br = (nt*8 + lg)*20 + ks8 + lq;
                unsigned bh0 = __float_as_uint(Whi[br]);
                unsigned bh1 = __float_as_uint(Whi[br + 4]);
                unsigned bl0 = __float_as_uint(Wlo[br]);
                unsigned bl1 = __float_as_uint(Wlo[br + 4]);
                mma16n8k8(acc[nt][0], acc[nt][1], acc[nt][2], acc[nt][3],
                          ah0, ah1, ah2, ah3, bh0, bh1);
                mma16n8k8(acc[nt][0], acc[nt][1], acc[nt][2], acc[nt][3],
                          ah0, ah1, ah2, ah3, bl0, bl1);
                mma16n8k8(acc[nt][0], acc[nt][1], acc[nt][2], acc[nt][3],
                          al0, al1, al2, al3, bh0, bh1);
            }
        }
    }

    int r_a = r0 + w16 + lg;
    int r_b = r_a + 8;
    #pragma unroll
    for (int nt = 0; nt < 8; nt++) {
        int c = c0 + nt*8 + 2*lq;
        float2 bv = *(const float2*)&bo[c];
        *(float2*)&out[(size_t)r_a * DD + c] =
            make_float2(acc[nt][0] + bv.x, acc[nt][1] + bv.y);
        *(float2*)&out[(size_t)r_b * DD + c] =
            make_float2(acc[nt][2] + bv.x, acc[nt][3] + bv.y);
    }
}

extern "C" void kernel_launch(void* const* d_in, const int* in_sizes, int n_in,
                              void* d_out, int out_size) {
    const float* x   = (const float*)d_in[0];
    const float* adj = (const float*)d_in[1];
    const float* Wq  = (const float*)d_in[2];
    const float* Wk  = (const float*)d_in[3];
    const float* Wv  = (const float*)d_in[4];
    const float* Wo  = (const float*)d_in[5];
    const float* bo  = (const float*)d_in[6];
    float* out = (float*)d_out;

    prep_kernel<<<896, 256>>>(x, adj, Wq, Wk, Wv);
    attn_kernel<<<dim3(NN/128, HH, BB*SPLIT), 256>>>();
    combine_kernel<<<(R_ROWS*8 + 255)/256, 256>>>();
    gemm_out<<<dim3(32, 4), 256>>>(Wo, bo, out);
}